// round 12
// baseline (speedup 1.0000x reference)
#include <cuda_runtime.h>
#include <mma.h>
#include <math.h>

using namespace nvcuda;

#define N_NODES 50000
#define N_EDGES 400000
#define ET (N_EDGES + N_NODES)   // 450000 edges incl. self-loops
#define TB 256
#define SCAN_B 1024
#define SCAN_G ((N_NODES + SCAN_B - 1) / SCAN_B)   // 49

// ---------------- scratch (device globals; no allocs allowed) ----------------
__device__ float g_xl [(size_t)N_NODES * 768];
__device__ float g_x1 [(size_t)N_NODES * 256];
__device__ float g_x2 [(size_t)N_NODES * 256];
__device__ float g_t32[(size_t)N_NODES * 32];
__device__ float g_xf0[(size_t)N_NODES * 1080];  // [gg | conv3 | xa1 | xa2]
__device__ float g_xf1[(size_t)N_NODES * 200];
__device__ float g_xf2[(size_t)N_NODES * 64];
__device__ float g_als[(size_t)N_NODES * 12];
__device__ float g_ald[(size_t)N_NODES * 12];
__device__ float g_m  [(size_t)N_NODES * 12];    // per-dst softmax max
__device__ float g_den[(size_t)N_NODES * 12];    // per-dst 1/sum
__device__ int   g_src[ET];
__device__ int   g_dst[ET];
__device__ int   g_deg[N_NODES];
__device__ int   g_rs [N_NODES + 1];
__device__ int   g_cur[N_NODES];
__device__ int   g_csr[ET];                      // CSR slot -> src node
__device__ int   g_bsum[SCAN_G];
__device__ int   g_boff[SCAN_G];
__device__ int   g_is64;

// ---------------- dtype probe ------------------------------------------------
__global__ void detect_dtype_k(const int* __restrict__ ei32) {
    int all_zero = 1;
#pragma unroll
    for (int i = 0; i < 16; i++)
        if (ei32[2 * i + 1] != 0) all_zero = 0;
    g_is64 = all_zero;
}

__global__ void zero_deg_k() {
    int i = blockIdx.x * blockDim.x + threadIdx.x;
    if (i < N_NODES) g_deg[i] = 0;
}

__global__ void prep_edges_k(const void* __restrict__ ei) {
    int i = blockIdx.x * blockDim.x + threadIdx.x;
    if (i >= ET) return;
    int s, d;
    if (i < N_EDGES) {
        if (g_is64) {
            const long long* p = (const long long*)ei;
            s = (int)p[i]; d = (int)p[N_EDGES + i];
        } else {
            const int* p = (const int*)ei;
            s = p[i]; d = p[N_EDGES + i];
        }
    } else {
        s = d = i - N_EDGES;
    }
    g_src[i] = s;
    g_dst[i] = d;
    atomicAdd(&g_deg[d], 1);
}

// ---------------- deterministic 3-phase scan ----------------------------------
__global__ void scan1_k() {
    __shared__ int sh[SCAN_B];
    int b = blockIdx.x, t = threadIdx.x;
    int idx = b * SCAN_B + t;
    int v = (idx < N_NODES) ? g_deg[idx] : 0;
    sh[t] = v;
    __syncthreads();
    for (int o = 1; o < SCAN_B; o <<= 1) {
        int u = (t >= o) ? sh[t - o] : 0;
        __syncthreads();
        sh[t] += u;
        __syncthreads();
    }
    if (idx < N_NODES) g_rs[idx] = sh[t] - v;
    if (t == SCAN_B - 1) g_bsum[b] = sh[t];
}

__global__ void scan2_k() {
    if (threadIdx.x == 0) {
        int run = 0;
        for (int b = 0; b < SCAN_G; b++) { g_boff[b] = run; run += g_bsum[b]; }
    }
}

__global__ void scan3_k() {
    int idx = blockIdx.x * SCAN_B + threadIdx.x;
    if (idx < N_NODES) {
        int v = g_rs[idx] + g_boff[blockIdx.x];
        g_rs[idx] = v;
        g_cur[idx] = v;
    }
    if (idx == 0) g_rs[N_NODES] = ET;
}

__global__ void scatter_k() {
    int e = blockIdx.x * blockDim.x + threadIdx.x;
    if (e >= ET) return;
    int pos = atomicAdd(&g_cur[g_dst[e]], 1);
    g_csr[pos] = g_src[e];
}

// ---------------- TF32 tensor-core GEMM, cp.async double-buffered, BK=32 ------
#define BM 128
#define BN 64
#define BK 32
#define A_LD 36
#define B_LD 72
#define A_STG (BM * A_LD)          // floats per A stage  = 4608
#define B_STG (BK * B_LD)          // floats per B stage  = 2304
#define GEMM_SMEM ((2 * A_STG + 2 * B_STG) * 4)   // 55296 bytes

__device__ __forceinline__ void cpa16(float* dst, const float* src, bool valid) {
    unsigned d = (unsigned)__cvta_generic_to_shared(dst);
    int sz = valid ? 16 : 0;                 // src-size 0 => zero-fill 16B
    asm volatile("cp.async.ca.shared.global [%0], [%1], 16, %2;\n"
                 :: "r"(d), "l"(src), "r"(sz));
}

// All call sites guarantee K%4==0, colOff%4==0, ldC%4==0 (vectorized epilogue).
// NOTE: no explicit fp32->tf32 rounding; HMMA truncates mantissa (ok @1e-3 gate).
__global__ void gemm_k(const float* __restrict__ A, const float* __restrict__ B,
                       const float* __restrict__ bias, float* __restrict__ C,
                       int Nr, int M, int K, int act, int ldC, int colOff) {
    extern __shared__ __align__(16) float smem_dyn[];
    float* As = smem_dyn;                     // [2][128][36]
    float* Bs = smem_dyn + 2 * A_STG;         // [2][32][72]
    float* Cs = smem_dyn;                     // [128][68] (aliases stages)
    int tid = threadIdx.x;
    int wid = tid >> 5;
    int wm = wid >> 1;
    int wn = wid & 1;
    int rowBase = blockIdx.y * BM;
    int colBase = blockIdx.x * BN;

    wmma::fragment<wmma::accumulator, 16, 16, 8, float> acc[2][2];
#pragma unroll
    for (int i = 0; i < 2; i++)
#pragma unroll
        for (int j = 0; j < 2; j++) wmma::fill_fragment(acc[i][j], 0.f);

    int nt = (M + BK - 1) / BK;

    auto load_tile = [&](int k0, int buf) {
#pragma unroll
        for (int i = tid; i < 1024; i += 256) {
            int r = i >> 3, c4 = i & 7;
            int gr = rowBase + r, gk = k0 + c4 * 4;
            bool v = (gr < Nr) && (gk + 4 <= M);
            const float* src = v ? (A + (size_t)gr * M + gk) : A;
            cpa16(As + buf * A_STG + r * A_LD + c4 * 4, src, v);
        }
#pragma unroll
        for (int i = tid; i < 512; i += 256) {
            int r = i >> 4, c4 = i & 15;
            int gk = k0 + r, gc = colBase + c4 * 4;
            bool v = (gk < M) && (gc + 4 <= K);
            const float* src = v ? (B + (size_t)gk * K + gc) : B;
            cpa16(Bs + buf * B_STG + r * B_LD + c4 * 4, src, v);
        }
        asm volatile("cp.async.commit_group;\n");
    };

    load_tile(0, 0);
    for (int t = 0; t < nt; t++) {
        if (t + 1 < nt) {
            load_tile((t + 1) * BK, (t + 1) & 1);
            asm volatile("cp.async.wait_group 1;\n");
        } else {
            asm volatile("cp.async.wait_group 0;\n");
        }
        __syncthreads();
        int buf = t & 1;
        float* Ab = As + buf * A_STG;
        float* Bb = Bs + buf * B_STG;
#pragma unroll
        for (int ks = 0; ks < 4; ks++) {
            wmma::fragment<wmma::matrix_a, 16, 16, 8, wmma::precision::tf32, wmma::row_major> af[2];
            wmma::fragment<wmma::matrix_b, 16, 16, 8, wmma::precision::tf32, wmma::row_major> bf[2];
#pragma unroll
            for (int i = 0; i < 2; i++)
                wmma::load_matrix_sync(af[i], Ab + (wm * 32 + i * 16) * A_LD + ks * 8, A_LD);
#pragma unroll
            for (int j = 0; j < 2; j++)
                wmma::load_matrix_sync(bf[j], Bb + (ks * 8) * B_LD + wn * 32 + j * 16, B_LD);
#pragma unroll
            for (int i = 0; i < 2; i++)
#pragma unroll
                for (int j = 0; j < 2; j++)
                    wmma::mma_sync(acc[i][j], af[i], bf[j], acc[i][j]);
        }
        __syncthreads();
    }

    // epilogue: stage accumulators into (aliased) Cs, then float4 global write
#pragma unroll
    for (int i = 0; i < 2; i++)
#pragma unroll
        for (int j = 0; j < 2; j++)
            wmma::store_matrix_sync(Cs + (wm * 32 + i * 16) * 68 + wn * 32 + j * 16,
                                    acc[i][j], 68, wmma::mem_row_major);
    __syncthreads();
    for (int i = tid; i < BM * BN / 4; i += 256) {
        int r = i >> 4;
        int c4 = (i & 15) << 2;
        int gr = rowBase + r, gc = colBase + c4;
        if (gr >= Nr || gc >= K) continue;
        float4 v = *(const float4*)(Cs + r * 68 + c4);
        if (bias) {
            float4 bb = *(const float4*)(bias + gc);
            v.x += bb.x; v.y += bb.y; v.z += bb.z; v.w += bb.w;
        }
        if (act) {
            v.x = fmaxf(v.x, 0.f); v.y = fmaxf(v.y, 0.f);
            v.z = fmaxf(v.z, 0.f); v.w = fmaxf(v.w, 0.f);
        }
        *(float4*)(C + (size_t)gr * ldC + colOff + gc) = v;
    }
}

// ---------------- per-node attention logits: warp per (n,h) -------------------
template <int H, int C>
__global__ void alpha_k(const float* __restrict__ xl,
                        const float* __restrict__ a_src,
                        const float* __restrict__ a_dst) {
    int gw = (blockIdx.x * blockDim.x + threadIdx.x) >> 5;
    int lane = threadIdx.x & 31;
    if (gw >= N_NODES * H) return;
    int n = gw / H, h = gw - n * H;
    const float* row = xl + (size_t)n * (H * C) + h * C;
    float s1 = 0.f, s2 = 0.f;
#pragma unroll
    for (int c = lane; c < C; c += 32) {
        float v = row[c];
        s1 += v * a_src[h * C + c];
        s2 += v * a_dst[h * C + c];
    }
#pragma unroll
    for (int o = 16; o; o >>= 1) {
        s1 += __shfl_down_sync(0xffffffffu, s1, o);
        s2 += __shfl_down_sync(0xffffffffu, s2, o);
    }
    if (lane == 0) { g_als[gw] = s1; g_ald[gw] = s2; }
}

__device__ __forceinline__ float lrelu(float v) { return v > 0.f ? v : 0.2f * v; }

// ---------------- stats: per-dst online softmax (m, 1/den) --------------------
template <int H>
__global__ void stats_k() {
    int wid = threadIdx.x >> 5, lane = threadIdx.x & 31;
    int d = blockIdx.x * 8 + wid;
    if (d >= N_NODES) return;
    int beg = g_rs[d], end = g_rs[d + 1];
    float aldv[H];
#pragma unroll
    for (int h = 0; h < H; h++) aldv[h] = g_ald[d * H + h];
    float m[H], s[H];
#pragma unroll
    for (int h = 0; h < H; h++) { m[h] = -1e30f; s[h] = 0.f; }
    for (int j = beg + lane; j < end; j += 32) {
        int src = g_csr[j];
#pragma unroll
        for (int h = 0; h < H; h++) {
            float v = lrelu(g_als[src * H + h] + aldv[h]);
            if (v > m[h]) { s[h] = s[h] * __expf(m[h] - v) + 1.f; m[h] = v; }
            else          { s[h] += __expf(v - m[h]); }
        }
    }
#pragma unroll
    for (int h = 0; h < H; h++) {
#pragma unroll
        for (int o = 16; o; o >>= 1) {
            float mo = __shfl_xor_sync(0xffffffffu, m[h], o);
            float so = __shfl_xor_sync(0xffffffffu, s[h], o);
            float M = fmaxf(m[h], mo);
            s[h] = s[h] * __expf(m[h] - M) + so * __expf(mo - M);
            m[h] = M;
        }
    }
    if (lane == 0) {
#pragma unroll
        for (int h = 0; h < H; h++) {
            g_m[d * H + h] = m[h];
            g_den[d * H + h] = 1.f / s[h];
        }
    }
}

// ---------------- agg: warp per (dst, 128-float chunk), x4 unrolled gather ----
template <int H, int C>
__global__ void agg_k(const float* __restrict__ xl, const float* __restrict__ bias,
                      float* __restrict__ out, int ldo, int colOff) {
    const int HC = H * C;
    const int CH = HC / 128;
    const int RS = HC / 4;                 // float4 row stride
    int w = (blockIdx.x * blockDim.x + threadIdx.x) >> 5;
    int lane = threadIdx.x & 31;
    if (w >= N_NODES * CH) return;
    int d = w / CH, c = w - d * CH;
    int beg = g_rs[d], end = g_rs[d + 1];
    int col = c * 128 + lane * 4;
    int hm = col / C;
    float ald  = g_ald[d * H + hm];
    float mref = g_m  [d * H + hm];
    float rden = g_den[d * H + hm];
    const float4* xbase = (const float4*)xl + (col >> 2);
    float4 acc = make_float4(0.f, 0.f, 0.f, 0.f);

    int j = beg;
    // ---- x4 unrolled: batch index loads, then als loads, then rows (MLP~4) ----
    for (; j + 4 <= end; j += 4) {
        int s0 = g_csr[j],     s1 = g_csr[j + 1];
        int s2 = g_csr[j + 2], s3 = g_csr[j + 3];
        float a0 = g_als[s0 * H + hm], a1 = g_als[s1 * H + hm];
        float a2 = g_als[s2 * H + hm], a3 = g_als[s3 * H + hm];
        float4 x0 = xbase[(size_t)s0 * RS];
        float4 x1 = xbase[(size_t)s1 * RS];
        float4 x2 = xbase[(size_t)s2 * RS];
        float4 x3 = xbase[(size_t)s3 * RS];
        float c0 = __expf(lrelu(a0 + ald) - mref) * rden;
        float c1 = __expf(lrelu(a1 + ald) - mref) * rden;
        float c2 = __expf(lrelu(a2 + ald) - mref) * rden;
        float c3 = __expf(lrelu(a3 + ald) - mref) * rden;
        acc.x += c0 * x0.x + c1 * x1.x + c2 * x2.x + c3 * x3.x;
        acc.y += c0 * x0.y + c1 * x1.y + c2 * x2.y + c3 * x3.y;
        acc.z += c0 * x0.z + c1 * x1.z + c2 * x2.z + c3 * x3.z;
        acc.w += c0 * x0.w + c1 * x1.w + c2 * x2.w + c3 * x3.w;
    }
    // ---- remainder ----
    for (; j < end; j++) {
        int src = g_csr[j];
        float v = lrelu(g_als[src * H + hm] + ald);
        float coef = __expf(v - mref) * rden;
        float4 xv = xbase[(size_t)src * RS];
        acc.x += coef * xv.x; acc.y += coef * xv.y;
        acc.z += coef * xv.z; acc.w += coef * xv.w;
    }

    float4 bb = *(const float4*)(bias + col);
    float4 r;
    r.x = fmaxf(acc.x + bb.x, 0.f);
    r.y = fmaxf(acc.y + bb.y, 0.f);
    r.z = fmaxf(acc.z + bb.z, 0.f);
    r.w = fmaxf(acc.w + bb.w, 0.f);
    *(float4*)(out + (size_t)d * ldo + colOff + col) = r;
}

// ---------------- final: sigmoid(dot(xf2[n,:64], w) + b) ----------------------
__global__ void final_k(const float* __restrict__ xf2, const float* __restrict__ w,
                        const float* __restrict__ b, float* __restrict__ out) {
    int gw = (blockIdx.x * blockDim.x + threadIdx.x) >> 5;
    int lane = threadIdx.x & 31;
    if (gw >= N_NODES) return;
    const float* r = xf2 + (size_t)gw * 64;
    float s = r[lane] * w[lane] + r[lane + 32] * w[lane + 32];
#pragma unroll
    for (int o = 16; o; o >>= 1) s += __shfl_down_sync(0xffffffffu, s, o);
    if (lane == 0) out[gw] = 1.f / (1.f + expf(-(s + b[0])));
}

// =============================================================================
static inline dim3 gemm_grid(int K) { return dim3((K + BN - 1) / BN, (N_NODES + BM - 1) / BM); }
static inline int cdiv(int a, int b) { return (a + b - 1) / b; }

extern "C" void kernel_launch(void* const* d_in, const int* in_sizes, int n_in,
                              void* d_out, int out_size) {
    const float* x  = (const float*)d_in[0];
    const void*  ei = d_in[1];
    const float *W1 = (const float*)d_in[2],  *as1 = (const float*)d_in[3],
                *ad1 = (const float*)d_in[4], *b1  = (const float*)d_in[5];
    const float *W2 = (const float*)d_in[6],  *as2 = (const float*)d_in[7],
                *ad2 = (const float*)d_in[8], *b2  = (const float*)d_in[9];
    const float *W3 = (const float*)d_in[10], *as3 = (const float*)d_in[11],
                *ad3 = (const float*)d_in[12], *b3 = (const float*)d_in[13];
    const float *ln1_w = (const float*)d_in[14], *ln1_b = (const float*)d_in[15];
    const float *ln2_w = (const float*)d_in[16], *ln2_b = (const float*)d_in[17];
    const float *la1_w = (const float*)d_in[18], *la1_b = (const float*)d_in[19];
    const float *la3_w = (const float*)d_in[20], *la3_b = (const float*)d_in[21];
    const float *lf1_w = (const float*)d_in[22], *lf1_b = (const float*)d_in[23];
    const float *lf2_w = (const float*)d_in[24], *lf2_b = (const float*)d_in[25];
    const float *lf3_w = (const float*)d_in[26], *lf3_b = (const float*)d_in[27];
    float* out = (float*)d_out;

    float *xl, *x1, *x2, *t32, *xf0, *xf1, *xf2;
    cudaGetSymbolAddress((void**)&xl,  g_xl);
    cudaGetSymbolAddress((void**)&x1,  g_x1);
    cudaGetSymbolAddress((void**)&x2,  g_x2);
    cudaGetSymbolAddress((void**)&t32, g_t32);
    cudaGetSymbolAddress((void**)&xf0, g_xf0);
    cudaGetSymbolAddress((void**)&xf1, g_xf1);
    cudaGetSymbolAddress((void**)&xf2, g_xf2);

    cudaFuncSetAttribute(gemm_k, cudaFuncAttributeMaxDynamicSharedMemorySize, GEMM_SMEM);

    // edge prep
    detect_dtype_k<<<1, 1>>>((const int*)ei);
    zero_deg_k<<<cdiv(N_NODES, TB), TB>>>();
    prep_edges_k<<<cdiv(ET, TB), TB>>>(ei);
    gemm_k<<<gemm_grid(256), TB, GEMM_SMEM>>>(x, W1, nullptr, xl, N_NODES, 16, 256, 0, 256, 0);
    scan1_k<<<SCAN_G, SCAN_B>>>();
    scan2_k<<<1, 32>>>();
    scan3_k<<<SCAN_G, SCAN_B>>>();
    scatter_k<<<cdiv(ET, TB), TB>>>();

    // ---- conv1: 16 -> 8x32 -> x1 ----
    alpha_k<8, 32><<<cdiv(N_NODES * 8 * 32, TB), TB>>>(xl, as1, ad1);
    stats_k<8><<<cdiv(N_NODES, 8), TB>>>();
    agg_k<8, 32><<<cdiv(N_NODES * 2 * 32, TB), TB>>>(xl, b1, x1, 256, 0);

    // dense gg path -> xf0[:, 0:32]
    gemm_k<<<gemm_grid(32), TB, GEMM_SMEM>>>(x,   ln1_w, ln1_b, t32, N_NODES, 16, 32, 1, 32, 0);
    gemm_k<<<gemm_grid(32), TB, GEMM_SMEM>>>(t32, ln2_w, ln2_b, xf0, N_NODES, 32, 32, 1, 1080, 0);

    // ---- conv2: 256 -> 8x32 -> x2 ----
    gemm_k<<<gemm_grid(256), TB, GEMM_SMEM>>>(x1, W2, nullptr, xl, N_NODES, 256, 256, 0, 256, 0);
    alpha_k<8, 32><<<cdiv(N_NODES * 8 * 32, TB), TB>>>(xl, as2, ad2);
    stats_k<8><<<cdiv(N_NODES, 8), TB>>>();
    agg_k<8, 32><<<cdiv(N_NODES * 2 * 32, TB), TB>>>(xl, b2, x2, 256, 0);

    // ---- conv3: 256 -> 12x64 -> xf0[:, 32:800] ----
    gemm_k<<<gemm_grid(768), TB, GEMM_SMEM>>>(x2, W3, nullptr, xl, N_NODES, 256, 768, 0, 768, 0);
    alpha_k<12, 64><<<cdiv(N_NODES * 12 * 32, TB), TB>>>(xl, as3, ad3);
    stats_k<12><<<cdiv(N_NODES, 8), TB>>>();
    agg_k<12, 64><<<cdiv(N_NODES * 6 * 32, TB), TB>>>(xl, b3, xf0, 1080, 32);

    // side dense paths -> xf0[:, 800:880], xf0[:, 880:1080]
    gemm_k<<<gemm_grid(80),  TB, GEMM_SMEM>>>(x1, la1_w, la1_b, xf0, N_NODES, 256, 80, 1, 1080, 800);
    gemm_k<<<gemm_grid(200), TB, GEMM_SMEM>>>(x2, la3_w, la3_b, xf0, N_NODES, 256, 200, 1, 1080, 880);

    // MLP head
    gemm_k<<<gemm_grid(200), TB, GEMM_SMEM>>>(xf0, lf1_w, lf1_b, xf1, N_NODES, 1080, 200, 1, 200, 0);
    gemm_k<<<gemm_grid(64),  TB, GEMM_SMEM>>>(xf1, lf2_w, lf2_b, xf2, N_NODES, 200, 64, 1, 64, 0);
    final_k<<<cdiv(N_NODES * 32, TB), TB>>>(xf2, lf3_w, lf3_b, out);
}

// round 13
// speedup vs baseline: 1.0485x; 1.0485x over previous
#include <cuda_runtime.h>
#include <cuda_fp16.h>
#include <mma.h>
#include <math.h>

using namespace nvcuda;

#define N_NODES 50000
#define N_EDGES 400000
#define ET (N_EDGES + N_NODES)   // 450000 edges incl. self-loops
#define TB 256
#define SCAN_B 1024
#define SCAN_G ((N_NODES + SCAN_B - 1) / SCAN_B)   // 49

// ---------------- scratch (device globals; no allocs allowed) ----------------
__device__ float  g_xl [(size_t)N_NODES * 256];   // conv1/2 transformed (fp32)
__device__ __half g_xlh[(size_t)N_NODES * 768];   // conv3 transformed (fp16)
__device__ float  g_x1 [(size_t)N_NODES * 256];
__device__ float  g_x2 [(size_t)N_NODES * 256];
__device__ float  g_t32[(size_t)N_NODES * 32];
__device__ float  g_xf0[(size_t)N_NODES * 1080];  // [gg | conv3 | xa1 | xa2]
__device__ float  g_xf1[(size_t)N_NODES * 200];
__device__ float  g_xf2[(size_t)N_NODES * 64];
__device__ float  g_als[(size_t)N_NODES * 12];
__device__ float  g_ald[(size_t)N_NODES * 12];
__device__ float  g_m  [(size_t)N_NODES * 12];    // per-dst softmax max
__device__ float  g_den[(size_t)N_NODES * 12];    // per-dst 1/sum
__device__ int    g_src[ET];
__device__ int    g_dst[ET];
__device__ int    g_deg[N_NODES];
__device__ int    g_rs [N_NODES + 1];
__device__ int    g_cur[N_NODES];
__device__ int    g_csr[ET];                      // CSR slot -> src node
__device__ int    g_bsum[SCAN_G];
__device__ int    g_boff[SCAN_G];
__device__ int    g_is64;

// ---------------- dtype probe ------------------------------------------------
__global__ void detect_dtype_k(const int* __restrict__ ei32) {
    int all_zero = 1;
#pragma unroll
    for (int i = 0; i < 16; i++)
        if (ei32[2 * i + 1] != 0) all_zero = 0;
    g_is64 = all_zero;
}

__global__ void zero_deg_k() {
    int i = blockIdx.x * blockDim.x + threadIdx.x;
    if (i < N_NODES) g_deg[i] = 0;
}

__global__ void prep_edges_k(const void* __restrict__ ei) {
    int i = blockIdx.x * blockDim.x + threadIdx.x;
    if (i >= ET) return;
    int s, d;
    if (i < N_EDGES) {
        if (g_is64) {
            const long long* p = (const long long*)ei;
            s = (int)p[i]; d = (int)p[N_EDGES + i];
        } else {
            const int* p = (const int*)ei;
            s = p[i]; d = p[N_EDGES + i];
        }
    } else {
        s = d = i - N_EDGES;
    }
    g_src[i] = s;
    g_dst[i] = d;
    atomicAdd(&g_deg[d], 1);
}

// ---------------- deterministic 3-phase scan ----------------------------------
__global__ void scan1_k() {
    __shared__ int sh[SCAN_B];
    int b = blockIdx.x, t = threadIdx.x;
    int idx = b * SCAN_B + t;
    int v = (idx < N_NODES) ? g_deg[idx] : 0;
    sh[t] = v;
    __syncthreads();
    for (int o = 1; o < SCAN_B; o <<= 1) {
        int u = (t >= o) ? sh[t - o] : 0;
        __syncthreads();
        sh[t] += u;
        __syncthreads();
    }
    if (idx < N_NODES) g_rs[idx] = sh[t] - v;
    if (t == SCAN_B - 1) g_bsum[b] = sh[t];
}

__global__ void scan2_k() {
    if (threadIdx.x == 0) {
        int run = 0;
        for (int b = 0; b < SCAN_G; b++) { g_boff[b] = run; run += g_bsum[b]; }
    }
}

__global__ void scan3_k() {
    int idx = blockIdx.x * SCAN_B + threadIdx.x;
    if (idx < N_NODES) {
        int v = g_rs[idx] + g_boff[blockIdx.x];
        g_rs[idx] = v;
        g_cur[idx] = v;
    }
    if (idx == 0) g_rs[N_NODES] = ET;
}

__global__ void scatter_k() {
    int e = blockIdx.x * blockDim.x + threadIdx.x;
    if (e >= ET) return;
    int pos = atomicAdd(&g_cur[g_dst[e]], 1);
    g_csr[pos] = g_src[e];
}

// ---------------- TF32 tensor-core GEMM, cp.async double-buffered, BK=32 ------
#define BM 128
#define BN 64
#define BK 32
#define A_LD 36
#define B_LD 72
#define A_STG (BM * A_LD)
#define B_STG (BK * B_LD)
#define GEMM_SMEM ((2 * A_STG + 2 * B_STG) * 4)   // 55296 bytes

__device__ __forceinline__ void cpa16(float* dst, const float* src, bool valid) {
    unsigned d = (unsigned)__cvta_generic_to_shared(dst);
    int sz = valid ? 16 : 0;
    asm volatile("cp.async.ca.shared.global [%0], [%1], 16, %2;\n"
                 :: "r"(d), "l"(src), "r"(sz));
}

// halfOut=1 => C is __half*, stores fp16 (conv3 xl). Else float4 stores.
// All call sites: K%4==0, colOff%4==0, ldC%4==0.
__global__ void gemm_k(const float* __restrict__ A, const float* __restrict__ B,
                       const float* __restrict__ bias, float* __restrict__ C,
                       int Nr, int M, int K, int act, int ldC, int colOff,
                       int halfOut) {
    extern __shared__ __align__(16) float smem_dyn[];
    float* As = smem_dyn;                     // [2][128][36]
    float* Bs = smem_dyn + 2 * A_STG;         // [2][32][72]
    float* Cs = smem_dyn;                     // [128][68] (aliases stages)
    int tid = threadIdx.x;
    int wid = tid >> 5;
    int wm = wid >> 1;
    int wn = wid & 1;
    int rowBase = blockIdx.y * BM;
    int colBase = blockIdx.x * BN;

    wmma::fragment<wmma::accumulator, 16, 16, 8, float> acc[2][2];
#pragma unroll
    for (int i = 0; i < 2; i++)
#pragma unroll
        for (int j = 0; j < 2; j++) wmma::fill_fragment(acc[i][j], 0.f);

    int nt = (M + BK - 1) / BK;

    auto load_tile = [&](int k0, int buf) {
#pragma unroll
        for (int i = tid; i < 1024; i += 256) {
            int r = i >> 3, c4 = i & 7;
            int gr = rowBase + r, gk = k0 + c4 * 4;
            bool v = (gr < Nr) && (gk + 4 <= M);
            const float* src = v ? (A + (size_t)gr * M + gk) : A;
            cpa16(As + buf * A_STG + r * A_LD + c4 * 4, src, v);
        }
#pragma unroll
        for (int i = tid; i < 512; i += 256) {
            int r = i >> 4, c4 = i & 15;
            int gk = k0 + r, gc = colBase + c4 * 4;
            bool v = (gk < M) && (gc + 4 <= K);
            const float* src = v ? (B + (size_t)gk * K + gc) : B;
            cpa16(Bs + buf * B_STG + r * B_LD + c4 * 4, src, v);
        }
        asm volatile("cp.async.commit_group;\n");
    };

    load_tile(0, 0);
    for (int t = 0; t < nt; t++) {
        if (t + 1 < nt) {
            load_tile((t + 1) * BK, (t + 1) & 1);
            asm volatile("cp.async.wait_group 1;\n");
        } else {
            asm volatile("cp.async.wait_group 0;\n");
        }
        __syncthreads();
        int buf = t & 1;
        float* Ab = As + buf * A_STG;
        float* Bb = Bs + buf * B_STG;
#pragma unroll
        for (int ks = 0; ks < 4; ks++) {
            wmma::fragment<wmma::matrix_a, 16, 16, 8, wmma::precision::tf32, wmma::row_major> af[2];
            wmma::fragment<wmma::matrix_b, 16, 16, 8, wmma::precision::tf32, wmma::row_major> bf[2];
#pragma unroll
            for (int i = 0; i < 2; i++)
                wmma::load_matrix_sync(af[i], Ab + (wm * 32 + i * 16) * A_LD + ks * 8, A_LD);
#pragma unroll
            for (int j = 0; j < 2; j++)
                wmma::load_matrix_sync(bf[j], Bb + (ks * 8) * B_LD + wn * 32 + j * 16, B_LD);
#pragma unroll
            for (int i = 0; i < 2; i++)
#pragma unroll
                for (int j = 0; j < 2; j++)
                    wmma::mma_sync(acc[i][j], af[i], bf[j], acc[i][j]);
        }
        __syncthreads();
    }

    // epilogue: stage accumulators into (aliased) Cs, then vectorized write
#pragma unroll
    for (int i = 0; i < 2; i++)
#pragma unroll
        for (int j = 0; j < 2; j++)
            wmma::store_matrix_sync(Cs + (wm * 32 + i * 16) * 68 + wn * 32 + j * 16,
                                    acc[i][j], 68, wmma::mem_row_major);
    __syncthreads();
    for (int i = tid; i < BM * BN / 4; i += 256) {
        int r = i >> 4;
        int c4 = (i & 15) << 2;
        int gr = rowBase + r, gc = colBase + c4;
        if (gr >= Nr || gc >= K) continue;
        float4 v = *(const float4*)(Cs + r * 68 + c4);
        if (bias) {
            float4 bb = *(const float4*)(bias + gc);
            v.x += bb.x; v.y += bb.y; v.z += bb.z; v.w += bb.w;
        }
        if (act) {
            v.x = fmaxf(v.x, 0.f); v.y = fmaxf(v.y, 0.f);
            v.z = fmaxf(v.z, 0.f); v.w = fmaxf(v.w, 0.f);
        }
        if (halfOut) {
            __half2* dst = (__half2*)((__half*)C + (size_t)gr * ldC + colOff + gc);
            dst[0] = __floats2half2_rn(v.x, v.y);
            dst[1] = __floats2half2_rn(v.z, v.w);
        } else {
            *(float4*)(C + (size_t)gr * ldC + colOff + gc) = v;
        }
    }
}

// ---------------- per-node attention logits: warp per (n,h), fp32 xl ----------
template <int H, int C>
__global__ void alpha_k(const float* __restrict__ xl,
                        const float* __restrict__ a_src,
                        const float* __restrict__ a_dst) {
    int gw = (blockIdx.x * blockDim.x + threadIdx.x) >> 5;
    int lane = threadIdx.x & 31;
    if (gw >= N_NODES * H) return;
    int n = gw / H, h = gw - n * H;
    const float* row = xl + (size_t)n * (H * C) + h * C;
    float s1 = 0.f, s2 = 0.f;
#pragma unroll
    for (int c = lane; c < C; c += 32) {
        float v = row[c];
        s1 += v * a_src[h * C + c];
        s2 += v * a_dst[h * C + c];
    }
#pragma unroll
    for (int o = 16; o; o >>= 1) {
        s1 += __shfl_down_sync(0xffffffffu, s1, o);
        s2 += __shfl_down_sync(0xffffffffu, s2, o);
    }
    if (lane == 0) { g_als[gw] = s1; g_ald[gw] = s2; }
}

// ---------------- alpha for fp16 xl (conv3) -----------------------------------
template <int H, int C>
__global__ void alpha_h_k(const __half* __restrict__ xl,
                          const float* __restrict__ a_src,
                          const float* __restrict__ a_dst) {
    int gw = (blockIdx.x * blockDim.x + threadIdx.x) >> 5;
    int lane = threadIdx.x & 31;
    if (gw >= N_NODES * H) return;
    int n = gw / H, h = gw - n * H;
    const __half* row = xl + (size_t)n * (H * C) + h * C;
    float s1 = 0.f, s2 = 0.f;
#pragma unroll
    for (int c = lane; c < C; c += 32) {
        float v = __half2float(row[c]);
        s1 += v * a_src[h * C + c];
        s2 += v * a_dst[h * C + c];
    }
#pragma unroll
    for (int o = 16; o; o >>= 1) {
        s1 += __shfl_down_sync(0xffffffffu, s1, o);
        s2 += __shfl_down_sync(0xffffffffu, s2, o);
    }
    if (lane == 0) { g_als[gw] = s1; g_ald[gw] = s2; }
}

__device__ __forceinline__ float lrelu(float v) { return v > 0.f ? v : 0.2f * v; }

// ---------------- stats: per-dst online softmax (m, 1/den) --------------------
template <int H>
__global__ void stats_k() {
    int wid = threadIdx.x >> 5, lane = threadIdx.x & 31;
    int d = blockIdx.x * 8 + wid;
    if (d >= N_NODES) return;
    int beg = g_rs[d], end = g_rs[d + 1];
    float aldv[H];
#pragma unroll
    for (int h = 0; h < H; h++) aldv[h] = g_ald[d * H + h];
    float m[H], s[H];
#pragma unroll
    for (int h = 0; h < H; h++) { m[h] = -1e30f; s[h] = 0.f; }
    for (int j = beg + lane; j < end; j += 32) {
        int src = g_csr[j];
#pragma unroll
        for (int h = 0; h < H; h++) {
            float v = lrelu(g_als[src * H + h] + aldv[h]);
            if (v > m[h]) { s[h] = s[h] * __expf(m[h] - v) + 1.f; m[h] = v; }
            else          { s[h] += __expf(v - m[h]); }
        }
    }
#pragma unroll
    for (int h = 0; h < H; h++) {
#pragma unroll
        for (int o = 16; o; o >>= 1) {
            float mo = __shfl_xor_sync(0xffffffffu, m[h], o);
            float so = __shfl_xor_sync(0xffffffffu, s[h], o);
            float M = fmaxf(m[h], mo);
            s[h] = s[h] * __expf(m[h] - M) + so * __expf(mo - M);
            m[h] = M;
        }
    }
    if (lane == 0) {
#pragma unroll
        for (int h = 0; h < H; h++) {
            g_m[d * H + h] = m[h];
            g_den[d * H + h] = 1.f / s[h];
        }
    }
}

// ---------------- agg (fp32 xl): warp per (dst, 128-float chunk) --------------
template <int H, int C>
__global__ void agg_k(const float* __restrict__ xl, const float* __restrict__ bias,
                      float* __restrict__ out, int ldo, int colOff) {
    const int HC = H * C;
    const int CH = HC / 128;
    const int RS = HC / 4;
    int w = (blockIdx.x * blockDim.x + threadIdx.x) >> 5;
    int lane = threadIdx.x & 31;
    if (w >= N_NODES * CH) return;
    int d = w / CH, c = w - d * CH;
    int beg = g_rs[d], end = g_rs[d + 1];
    int col = c * 128 + lane * 4;
    int hm = col / C;
    float ald  = g_ald[d * H + hm];
    float mref = g_m  [d * H + hm];
    float rden = g_den[d * H + hm];
    const float4* xbase = (const float4*)xl + (col >> 2);
    float4 acc = make_float4(0.f, 0.f, 0.f, 0.f);
    for (int j = beg; j < end; j++) {
        int src = g_csr[j];
        float v = lrelu(g_als[src * H + hm] + ald);
        float coef = __expf(v - mref) * rden;
        float4 xv = xbase[(size_t)src * RS];
        acc.x += coef * xv.x; acc.y += coef * xv.y;
        acc.z += coef * xv.z; acc.w += coef * xv.w;
    }
    float4 bb = *(const float4*)(bias + col);
    float4 r;
    r.x = fmaxf(acc.x + bb.x, 0.f);
    r.y = fmaxf(acc.y + bb.y, 0.f);
    r.z = fmaxf(acc.z + bb.z, 0.f);
    r.w = fmaxf(acc.w + bb.w, 0.f);
    *(float4*)(out + (size_t)d * ldo + colOff + col) = r;
}

// ---------------- agg (fp16 xl, conv3): warp per (dst, 128-elem chunk) --------
template <int H, int C>
__global__ void agg_h_k(const __half* __restrict__ xl, const float* __restrict__ bias,
                        float* __restrict__ out, int ldo, int colOff) {
    const int HC = H * C;
    const int CH = HC / 128;
    int w = (blockIdx.x * blockDim.x + threadIdx.x) >> 5;
    int lane = threadIdx.x & 31;
    if (w >= N_NODES * CH) return;
    int d = w / CH, c = w - d * CH;
    int beg = g_rs[d], end = g_rs[d + 1];
    int col = c * 128 + lane * 4;
    int hm = col / C;
    float ald  = g_ald[d * H + hm];
    float mref = g_m  [d * H + hm];
    float rden = g_den[d * H + hm];
    // lane's 4 halfs start at element `col` within the row (8B aligned)
    float4 acc = make_float4(0.f, 0.f, 0.f, 0.f);
    for (int j = beg; j < end; j++) {
        int src = g_csr[j];
        float v = lrelu(g_als[src * H + hm] + ald);
        float coef = __expf(v - mref) * rden;
        const __half2* xr = (const __half2*)(xl + (size_t)src * HC + col);
        float2 p0 = __half22float2(xr[0]);
        float2 p1 = __half22float2(xr[1]);
        acc.x += coef * p0.x; acc.y += coef * p0.y;
        acc.z += coef * p1.x; acc.w += coef * p1.y;
    }
    float4 bb = *(const float4*)(bias + col);
    float4 r;
    r.x = fmaxf(acc.x + bb.x, 0.f);
    r.y = fmaxf(acc.y + bb.y, 0.f);
    r.z = fmaxf(acc.z + bb.z, 0.f);
    r.w = fmaxf(acc.w + bb.w, 0.f);
    *(float4*)(out + (size_t)d * ldo + colOff + col) = r;
}

// ---------------- final: sigmoid(dot(xf2[n,:64], w) + b) ----------------------
__global__ void final_k(const float* __restrict__ xf2, const float* __restrict__ w,
                        const float* __restrict__ b, float* __restrict__ out) {
    int gw = (blockIdx.x * blockDim.x + threadIdx.x) >> 5;
    int lane = threadIdx.x & 31;
    if (gw >= N_NODES) return;
    const float* r = xf2 + (size_t)gw * 64;
    float s = r[lane] * w[lane] + r[lane + 32] * w[lane + 32];
#pragma unroll
    for (int o = 16; o; o >>= 1) s += __shfl_down_sync(0xffffffffu, s, o);
    if (lane == 0) out[gw] = 1.f / (1.f + expf(-(s + b[0])));
}

// =============================================================================
static inline dim3 gemm_grid(int K) { return dim3((K + BN - 1) / BN, (N_NODES + BM - 1) / BM); }
static inline int cdiv(int a, int b) { return (a + b - 1) / b; }

extern "C" void kernel_launch(void* const* d_in, const int* in_sizes, int n_in,
                              void* d_out, int out_size) {
    const float* x  = (const float*)d_in[0];
    const void*  ei = d_in[1];
    const float *W1 = (const float*)d_in[2],  *as1 = (const float*)d_in[3],
                *ad1 = (const float*)d_in[4], *b1  = (const float*)d_in[5];
    const float *W2 = (const float*)d_in[6],  *as2 = (const float*)d_in[7],
                *ad2 = (const float*)d_in[8], *b2  = (const float*)d_in[9];
    const float *W3 = (const float*)d_in[10], *as3 = (const float*)d_in[11],
                *ad3 = (const float*)d_in[12], *b3 = (const float*)d_in[13];
    const float *ln1_w = (const float*)d_in[14], *ln1_b = (const float*)d_in[15];
    const float *ln2_w = (const float*)d_in[16], *ln2_b = (const float*)d_in[17];
    const float *la1_w = (const float*)d_in[18], *la1_b = (const float*)d_in[19];
    const float *la3_w = (const float*)d_in[20], *la3_b = (const float*)d_in[21];
    const float *lf1_w = (const float*)d_in[22], *lf1_b = (const float*)d_in[23];
    const float *lf2_w = (const float*)d_in[24], *lf2_b = (const float*)d_in[25];
    const float *lf3_w = (const float*)d_in[26], *lf3_b = (const float*)d_in[27];
    float* out = (float*)d_out;

    float *xl, *x1, *x2, *t32, *xf0, *xf1, *xf2;
    __half* xlh;
    cudaGetSymbolAddress((void**)&xl,  g_xl);
    cudaGetSymbolAddress((void**)&xlh, g_xlh);
    cudaGetSymbolAddress((void**)&x1,  g_x1);
    cudaGetSymbolAddress((void**)&x2,  g_x2);
    cudaGetSymbolAddress((void**)&t32, g_t32);
    cudaGetSymbolAddress((void**)&xf0, g_xf0);
    cudaGetSymbolAddress((void**)&xf1, g_xf1);
    cudaGetSymbolAddress((void**)&xf2, g_xf2);

    cudaFuncSetAttribute(gemm_k, cudaFuncAttributeMaxDynamicSharedMemorySize, GEMM_SMEM);

    // edge prep
    detect_dtype_k<<<1, 1>>>((const int*)ei);
    zero_deg_k<<<cdiv(N_NODES, TB), TB>>>();
    prep_edges_k<<<cdiv(ET, TB), TB>>>(ei);
    gemm_k<<<gemm_grid(256), TB, GEMM_SMEM>>>(x, W1, nullptr, xl, N_NODES, 16, 256, 0, 256, 0, 0);
    scan1_k<<<SCAN_G, SCAN_B>>>();
    scan2_k<<<1, 32>>>();
    scan3_k<<<SCAN_G, SCAN_B>>>();
    scatter_k<<<cdiv(ET, TB), TB>>>();

    // ---- conv1: 16 -> 8x32 -> x1 ----
    alpha_k<8, 32><<<cdiv(N_NODES * 8 * 32, TB), TB>>>(xl, as1, ad1);
    stats_k<8><<<cdiv(N_NODES, 8), TB>>>();
    agg_k<8, 32><<<cdiv(N_NODES * 2 * 32, TB), TB>>>(xl, b1, x1, 256, 0);

    // dense gg path -> xf0[:, 0:32]
    gemm_k<<<gemm_grid(32), TB, GEMM_SMEM>>>(x,   ln1_w, ln1_b, t32, N_NODES, 16, 32, 1, 32, 0, 0);
    gemm_k<<<gemm_grid(32), TB, GEMM_SMEM>>>(t32, ln2_w, ln2_b, xf0, N_NODES, 32, 32, 1, 1080, 0, 0);

    // ---- conv2: 256 -> 8x32 -> x2 ----
    gemm_k<<<gemm_grid(256), TB, GEMM_SMEM>>>(x1, W2, nullptr, xl, N_NODES, 256, 256, 0, 256, 0, 0);
    alpha_k<8, 32><<<cdiv(N_NODES * 8 * 32, TB), TB>>>(xl, as2, ad2);
    stats_k<8><<<cdiv(N_NODES, 8), TB>>>();
    agg_k<8, 32><<<cdiv(N_NODES * 2 * 32, TB), TB>>>(xl, b2, x2, 256, 0);

    // ---- conv3: 256 -> 12x64, xl stored fp16 -> xf0[:, 32:800] ----
    gemm_k<<<gemm_grid(768), TB, GEMM_SMEM>>>(x2, W3, nullptr, (float*)xlh, N_NODES, 256, 768, 0, 768, 0, 1);
    alpha_h_k<12, 64><<<cdiv(N_NODES * 12 * 32, TB), TB>>>(xlh, as3, ad3);
    stats_k<12><<<cdiv(N_NODES, 8), TB>>>();
    agg_h_k<12, 64><<<cdiv(N_NODES * 6 * 32, TB), TB>>>(xlh, b3, xf0, 1080, 32);

    // side dense paths -> xf0[:, 800:880], xf0[:, 880:1080]
    gemm_k<<<gemm_grid(80),  TB, GEMM_SMEM>>>(x1, la1_w, la1_b, xf0, N_NODES, 256, 80, 1, 1080, 800, 0);
    gemm_k<<<gemm_grid(200), TB, GEMM_SMEM>>>(x2, la3_w, la3_b, xf0, N_NODES, 256, 200, 1, 1080, 880, 0);

    // MLP head
    gemm_k<<<gemm_grid(200), TB, GEMM_SMEM>>>(xf0, lf1_w, lf1_b, xf1, N_NODES, 1080, 200, 1, 200, 0, 0);
    gemm_k<<<gemm_grid(64),  TB, GEMM_SMEM>>>(xf1, lf2_w, lf2_b, xf2, N_NODES, 200, 64, 1, 64, 0, 0);
    final_k<<<cdiv(N_NODES * 32, TB), TB>>>(xf2, lf3_w, lf3_b, out);
}

// round 14
// speedup vs baseline: 1.1160x; 1.0644x over previous
#include <cuda_runtime.h>
#include <cuda_fp16.h>
#include <mma.h>
#include <math.h>

using namespace nvcuda;

#define N_NODES 50000
#define N_EDGES 400000
#define ET (N_EDGES + N_NODES)   // 450000 edges incl. self-loops
#define TB 256
#define SCAN_B 1024
#define SCAN_G ((N_NODES + SCAN_B - 1) / SCAN_B)   // 49

// ---------------- scratch (device globals; no allocs allowed) ----------------
__device__ float  g_xl [(size_t)N_NODES * 256];   // conv1/2 transformed (fp32)
__device__ __half g_xlh[(size_t)N_NODES * 768];   // conv3 transformed (fp16)
__device__ float  g_x1 [(size_t)N_NODES * 256];
__device__ float  g_x2 [(size_t)N_NODES * 256];
__device__ float  g_t32[(size_t)N_NODES * 32];
__device__ float  g_xf0[(size_t)N_NODES * 1080];  // [gg | conv3 | xa1 | xa2]
__device__ float  g_xf1[(size_t)N_NODES * 200];
__device__ float  g_xf2[(size_t)N_NODES * 64];
__device__ float  g_als[(size_t)N_NODES * 12];
__device__ float  g_ald[(size_t)N_NODES * 12];
__device__ float  g_m  [(size_t)N_NODES * 12];    // per-dst softmax max
__device__ float  g_den[(size_t)N_NODES * 12];    // per-dst 1/sum
__device__ int    g_src[ET];
__device__ int    g_dst[ET];
__device__ int    g_deg[N_NODES];
__device__ int    g_rs [N_NODES + 1];
__device__ int    g_cur[N_NODES];
__device__ int    g_csr[ET];                      // CSR slot -> src node
__device__ int    g_bsum[SCAN_G];
__device__ int    g_boff[SCAN_G];
__device__ int    g_is64;

// ---------------- dtype probe ------------------------------------------------
__global__ void detect_dtype_k(const int* __restrict__ ei32) {
    int all_zero = 1;
#pragma unroll
    for (int i = 0; i < 16; i++)
        if (ei32[2 * i + 1] != 0) all_zero = 0;
    g_is64 = all_zero;
}

__global__ void zero_deg_k() {
    int i = blockIdx.x * blockDim.x + threadIdx.x;
    if (i < N_NODES) g_deg[i] = 0;
}

__global__ void prep_edges_k(const void* __restrict__ ei) {
    int i = blockIdx.x * blockDim.x + threadIdx.x;
    if (i >= ET) return;
    int s, d;
    if (i < N_EDGES) {
        if (g_is64) {
            const long long* p = (const long long*)ei;
            s = (int)p[i]; d = (int)p[N_EDGES + i];
        } else {
            const int* p = (const int*)ei;
            s = p[i]; d = p[N_EDGES + i];
        }
    } else {
        s = d = i - N_EDGES;
    }
    g_src[i] = s;
    g_dst[i] = d;
    atomicAdd(&g_deg[d], 1);
}

// ---------------- deterministic 3-phase scan ----------------------------------
__global__ void scan1_k() {
    __shared__ int sh[SCAN_B];
    int b = blockIdx.x, t = threadIdx.x;
    int idx = b * SCAN_B + t;
    int v = (idx < N_NODES) ? g_deg[idx] : 0;
    sh[t] = v;
    __syncthreads();
    for (int o = 1; o < SCAN_B; o <<= 1) {
        int u = (t >= o) ? sh[t - o] : 0;
        __syncthreads();
        sh[t] += u;
        __syncthreads();
    }
    if (idx < N_NODES) g_rs[idx] = sh[t] - v;
    if (t == SCAN_B - 1) g_bsum[b] = sh[t];
}

__global__ void scan2_k() {
    if (threadIdx.x == 0) {
        int run = 0;
        for (int b = 0; b < SCAN_G; b++) { g_boff[b] = run; run += g_bsum[b]; }
    }
}

__global__ void scan3_k() {
    int idx = blockIdx.x * SCAN_B + threadIdx.x;
    if (idx < N_NODES) {
        int v = g_rs[idx] + g_boff[blockIdx.x];
        g_rs[idx] = v;
        g_cur[idx] = v;
    }
    if (idx == 0) g_rs[N_NODES] = ET;
}

__global__ void scatter_k() {
    int e = blockIdx.x * blockDim.x + threadIdx.x;
    if (e >= ET) return;
    int pos = atomicAdd(&g_cur[g_dst[e]], 1);
    g_csr[pos] = g_src[e];
}

// ---------------- TF32 tensor-core GEMM + fused epilogues ---------------------
#define BM 128
#define BN 64
#define BK 32
#define A_LD 36
#define B_LD 72
#define A_STG (BM * A_LD)
#define B_STG (BK * B_LD)
#define GEMM_SMEM ((2 * A_STG + 2 * B_STG) * 4)   // 55296 bytes

__device__ __forceinline__ void cpa16(float* dst, const float* src, bool valid) {
    unsigned d = (unsigned)__cvta_generic_to_shared(dst);
    int sz = valid ? 16 : 0;
    asm volatile("cp.async.ca.shared.global [%0], [%1], 16, %2;\n"
                 :: "r"(d), "l"(src), "r"(sz));
}

// halfOut=1 => C is __half* (conv3 xl).
// aSrc/aDst != null => fused GAT alpha: each 64-col tile covers whole heads
//   (Cc=32 or 64, colOff=0) -> exclusive per-(row,head) writes to g_als/g_ald.
// finW != null => fused final head (requires single column tile, K<=BN):
//   out[row] = sigmoid(dot(actRow, finW) + finB).
__global__ void gemm_k(const float* __restrict__ A, const float* __restrict__ B,
                       const float* __restrict__ bias, float* __restrict__ C,
                       int Nr, int M, int K, int act, int ldC, int colOff,
                       int halfOut,
                       const float* __restrict__ aSrc, const float* __restrict__ aDst,
                       int Hh, int Cc,
                       const float* __restrict__ finW, const float* __restrict__ finB,
                       float* __restrict__ finOut) {
    extern __shared__ __align__(16) float smem_dyn[];
    float* As = smem_dyn;                     // [2][128][36]
    float* Bs = smem_dyn + 2 * A_STG;         // [2][32][72]
    float* Cs = smem_dyn;                     // [128][68] (aliases stages)
    int tid = threadIdx.x;
    int wid = tid >> 5;
    int wm = wid >> 1;
    int wn = wid & 1;
    int rowBase = blockIdx.y * BM;
    int colBase = blockIdx.x * BN;

    wmma::fragment<wmma::accumulator, 16, 16, 8, float> acc[2][2];
#pragma unroll
    for (int i = 0; i < 2; i++)
#pragma unroll
        for (int j = 0; j < 2; j++) wmma::fill_fragment(acc[i][j], 0.f);

    int nt = (M + BK - 1) / BK;

    auto load_tile = [&](int k0, int buf) {
#pragma unroll
        for (int i = tid; i < 1024; i += 256) {
            int r = i >> 3, c4 = i & 7;
            int gr = rowBase + r, gk = k0 + c4 * 4;
            bool v = (gr < Nr) && (gk + 4 <= M);
            const float* src = v ? (A + (size_t)gr * M + gk) : A;
            cpa16(As + buf * A_STG + r * A_LD + c4 * 4, src, v);
        }
#pragma unroll
        for (int i = tid; i < 512; i += 256) {
            int r = i >> 4, c4 = i & 15;
            int gk = k0 + r, gc = colBase + c4 * 4;
            bool v = (gk < M) && (gc + 4 <= K);
            const float* src = v ? (B + (size_t)gk * K + gc) : B;
            cpa16(Bs + buf * B_STG + r * B_LD + c4 * 4, src, v);
        }
        asm volatile("cp.async.commit_group;\n");
    };

    load_tile(0, 0);
    for (int t = 0; t < nt; t++) {
        if (t + 1 < nt) {
            load_tile((t + 1) * BK, (t + 1) & 1);
            asm volatile("cp.async.wait_group 1;\n");
        } else {
            asm volatile("cp.async.wait_group 0;\n");
        }
        __syncthreads();
        int buf = t & 1;
        float* Ab = As + buf * A_STG;
        float* Bb = Bs + buf * B_STG;
#pragma unroll
        for (int ks = 0; ks < 4; ks++) {
            wmma::fragment<wmma::matrix_a, 16, 16, 8, wmma::precision::tf32, wmma::row_major> af[2];
            wmma::fragment<wmma::matrix_b, 16, 16, 8, wmma::precision::tf32, wmma::row_major> bf[2];
#pragma unroll
            for (int i = 0; i < 2; i++)
                wmma::load_matrix_sync(af[i], Ab + (wm * 32 + i * 16) * A_LD + ks * 8, A_LD);
#pragma unroll
            for (int j = 0; j < 2; j++)
                wmma::load_matrix_sync(bf[j], Bb + (ks * 8) * B_LD + wn * 32 + j * 16, B_LD);
#pragma unroll
            for (int i = 0; i < 2; i++)
#pragma unroll
                for (int j = 0; j < 2; j++)
                    wmma::mma_sync(acc[i][j], af[i], bf[j], acc[i][j]);
        }
        __syncthreads();
    }

    // stage accumulators into (aliased) Cs
#pragma unroll
    for (int i = 0; i < 2; i++)
#pragma unroll
        for (int j = 0; j < 2; j++)
            wmma::store_matrix_sync(Cs + (wm * 32 + i * 16) * 68 + wn * 32 + j * 16,
                                    acc[i][j], 68, wmma::mem_row_major);
    __syncthreads();

    // apply bias + act in-place in Cs (so fused epilogues see final values)
    for (int i = tid; i < BM * BN / 4; i += 256) {
        int r = i >> 4;
        int c4 = (i & 15) << 2;
        int gc = colBase + c4;
        if (gc >= K) continue;
        float4 v = *(const float4*)(Cs + r * 68 + c4);
        if (bias) {
            float4 bb = *(const float4*)(bias + gc);
            v.x += bb.x; v.y += bb.y; v.z += bb.z; v.w += bb.w;
        }
        if (act) {
            v.x = fmaxf(v.x, 0.f); v.y = fmaxf(v.y, 0.f);
            v.z = fmaxf(v.z, 0.f); v.w = fmaxf(v.w, 0.f);
        }
        *(float4*)(Cs + r * 68 + c4) = v;
    }
    __syncthreads();

    // main store
    for (int i = tid; i < BM * BN / 4; i += 256) {
        int r = i >> 4;
        int c4 = (i & 15) << 2;
        int gr = rowBase + r, gc = colBase + c4;
        if (gr >= Nr || gc >= K) continue;
        float4 v = *(const float4*)(Cs + r * 68 + c4);
        if (halfOut) {
            __half2* dst = (__half2*)((__half*)C + (size_t)gr * ldC + colOff + gc);
            dst[0] = __floats2half2_rn(v.x, v.y);
            dst[1] = __floats2half2_rn(v.z, v.w);
        } else {
            *(float4*)(C + (size_t)gr * ldC + colOff + gc) = v;
        }
    }

    // fused GAT alpha: heads fully contained in this 64-col tile
    if (aSrc) {
        int nh = BN / Cc;                      // heads in this tile (1 or 2)
        for (int t2 = tid; t2 < BM * nh; t2 += 256) {
            int r = t2 % BM, hl = t2 / BM;
            int gr = rowBase + r;
            int h0 = colBase / Cc + hl;
            if (gr >= Nr || h0 >= Hh) continue;
            float s1 = 0.f, s2 = 0.f;
            const float* cr = Cs + r * 68 + hl * Cc;
            const float* asr = aSrc + h0 * Cc;
            const float* adr = aDst + h0 * Cc;
            for (int cc = 0; cc < Cc; cc++) {
                float v = cr[cc];
                s1 += v * asr[cc];
                s2 += v * adr[cc];
            }
            g_als[gr * Hh + h0] = s1;
            g_ald[gr * Hh + h0] = s2;
        }
    }

    // fused final head (single column tile; K<=64)
    if (finW) {
        for (int r = tid; r < BM; r += 256) {
            int gr = rowBase + r;
            if (gr >= Nr) continue;
            float s = 0.f;
            const float* cr = Cs + r * 68;
            for (int cc = 0; cc < K; cc++) s += cr[cc] * finW[cc];
            finOut[gr] = 1.f / (1.f + expf(-(s + finB[0])));
        }
    }
}

__device__ __forceinline__ float lrelu(float v) { return v > 0.f ? v : 0.2f * v; }

// ---------------- stats: per-dst online softmax (m, 1/den) --------------------
template <int H>
__global__ void stats_k() {
    int wid = threadIdx.x >> 5, lane = threadIdx.x & 31;
    int d = blockIdx.x * 8 + wid;
    if (d >= N_NODES) return;
    int beg = g_rs[d], end = g_rs[d + 1];
    float aldv[H];
#pragma unroll
    for (int h = 0; h < H; h++) aldv[h] = g_ald[d * H + h];
    float m[H], s[H];
#pragma unroll
    for (int h = 0; h < H; h++) { m[h] = -1e30f; s[h] = 0.f; }
    for (int j = beg + lane; j < end; j += 32) {
        int src = g_csr[j];
#pragma unroll
        for (int h = 0; h < H; h++) {
            float v = lrelu(g_als[src * H + h] + aldv[h]);
            if (v > m[h]) { s[h] = s[h] * __expf(m[h] - v) + 1.f; m[h] = v; }
            else          { s[h] += __expf(v - m[h]); }
        }
    }
#pragma unroll
    for (int h = 0; h < H; h++) {
#pragma unroll
        for (int o = 16; o; o >>= 1) {
            float mo = __shfl_xor_sync(0xffffffffu, m[h], o);
            float so = __shfl_xor_sync(0xffffffffu, s[h], o);
            float M = fmaxf(m[h], mo);
            s[h] = s[h] * __expf(m[h] - M) + so * __expf(mo - M);
            m[h] = M;
        }
    }
    if (lane == 0) {
#pragma unroll
        for (int h = 0; h < H; h++) {
            g_m[d * H + h] = m[h];
            g_den[d * H + h] = 1.f / s[h];
        }
    }
}

// ---------------- agg (fp32 xl): warp per (dst, 128-float chunk) --------------
template <int H, int C>
__global__ void agg_k(const float* __restrict__ xl, const float* __restrict__ bias,
                      float* __restrict__ out, int ldo, int colOff) {
    const int HC = H * C;
    const int CH = HC / 128;
    const int RS = HC / 4;
    int w = (blockIdx.x * blockDim.x + threadIdx.x) >> 5;
    int lane = threadIdx.x & 31;
    if (w >= N_NODES * CH) return;
    int d = w / CH, c = w - d * CH;
    int beg = g_rs[d], end = g_rs[d + 1];
    int col = c * 128 + lane * 4;
    int hm = col / C;
    float ald  = g_ald[d * H + hm];
    float mref = g_m  [d * H + hm];
    float rden = g_den[d * H + hm];
    const float4* xbase = (const float4*)xl + (col >> 2);
    float4 acc = make_float4(0.f, 0.f, 0.f, 0.f);
    for (int j = beg; j < end; j++) {
        int src = g_csr[j];
        float v = lrelu(g_als[src * H + hm] + ald);
        float coef = __expf(v - mref) * rden;
        float4 xv = xbase[(size_t)src * RS];
        acc.x += coef * xv.x; acc.y += coef * xv.y;
        acc.z += coef * xv.z; acc.w += coef * xv.w;
    }
    float4 bb = *(const float4*)(bias + col);
    float4 r;
    r.x = fmaxf(acc.x + bb.x, 0.f);
    r.y = fmaxf(acc.y + bb.y, 0.f);
    r.z = fmaxf(acc.z + bb.z, 0.f);
    r.w = fmaxf(acc.w + bb.w, 0.f);
    *(float4*)(out + (size_t)d * ldo + colOff + col) = r;
}

// ---------------- agg (fp16 xl, conv3): warp per (dst, 128-elem chunk) --------
template <int H, int C>
__global__ void agg_h_k(const __half* __restrict__ xl, const float* __restrict__ bias,
                        float* __restrict__ out, int ldo, int colOff) {
    const int HC = H * C;
    const int CH = HC / 128;
    int w = (blockIdx.x * blockDim.x + threadIdx.x) >> 5;
    int lane = threadIdx.x & 31;
    if (w >= N_NODES * CH) return;
    int d = w / CH, c = w - d * CH;
    int beg = g_rs[d], end = g_rs[d + 1];
    int col = c * 128 + lane * 4;
    int hm = col / C;
    float ald  = g_ald[d * H + hm];
    float mref = g_m  [d * H + hm];
    float rden = g_den[d * H + hm];
    float4 acc = make_float4(0.f, 0.f, 0.f, 0.f);
    for (int j = beg; j < end; j++) {
        int src = g_csr[j];
        float v = lrelu(g_als[src * H + hm] + ald);
        float coef = __expf(v - mref) * rden;
        const __half2* xr = (const __half2*)(xl + (size_t)src * HC + col);
        float2 p0 = __half22float2(xr[0]);
        float2 p1 = __half22float2(xr[1]);
        acc.x += coef * p0.x; acc.y += coef * p0.y;
        acc.z += coef * p1.x; acc.w += coef * p1.y;
    }
    float4 bb = *(const float4*)(bias + col);
    float4 r;
    r.x = fmaxf(acc.x + bb.x, 0.f);
    r.y = fmaxf(acc.y + bb.y, 0.f);
    r.z = fmaxf(acc.z + bb.z, 0.f);
    r.w = fmaxf(acc.w + bb.w, 0.f);
    *(float4*)(out + (size_t)d * ldo + colOff + col) = r;
}

// =============================================================================
static inline dim3 gemm_grid(int K) { return dim3((K + BN - 1) / BN, (N_NODES + BM - 1) / BM); }
static inline int cdiv(int a, int b) { return (a + b - 1) / b; }
#define NOFUSE nullptr, nullptr, 0, 0, nullptr, nullptr, nullptr

extern "C" void kernel_launch(void* const* d_in, const int* in_sizes, int n_in,
                              void* d_out, int out_size) {
    const float* x  = (const float*)d_in[0];
    const void*  ei = d_in[1];
    const float *W1 = (const float*)d_in[2],  *as1 = (const float*)d_in[3],
                *ad1 = (const float*)d_in[4], *b1  = (const float*)d_in[5];
    const float *W2 = (const float*)d_in[6],  *as2 = (const float*)d_in[7],
                *ad2 = (const float*)d_in[8], *b2  = (const float*)d_in[9];
    const float *W3 = (const float*)d_in[10], *as3 = (const float*)d_in[11],
                *ad3 = (const float*)d_in[12], *b3 = (const float*)d_in[13];
    const float *ln1_w = (const float*)d_in[14], *ln1_b = (const float*)d_in[15];
    const float *ln2_w = (const float*)d_in[16], *ln2_b = (const float*)d_in[17];
    const float *la1_w = (const float*)d_in[18], *la1_b = (const float*)d_in[19];
    const float *la3_w = (const float*)d_in[20], *la3_b = (const float*)d_in[21];
    const float *lf1_w = (const float*)d_in[22], *lf1_b = (const float*)d_in[23];
    const float *lf2_w = (const float*)d_in[24], *lf2_b = (const float*)d_in[25];
    const float *lf3_w = (const float*)d_in[26], *lf3_b = (const float*)d_in[27];
    float* out = (float*)d_out;

    float *xl, *x1, *x2, *t32, *xf0, *xf1, *xf2;
    __half* xlh;
    cudaGetSymbolAddress((void**)&xl,  g_xl);
    cudaGetSymbolAddress((void**)&xlh, g_xlh);
    cudaGetSymbolAddress((void**)&x1,  g_x1);
    cudaGetSymbolAddress((void**)&x2,  g_x2);
    cudaGetSymbolAddress((void**)&t32, g_t32);
    cudaGetSymbolAddress((void**)&xf0, g_xf0);
    cudaGetSymbolAddress((void**)&xf1, g_xf1);
    cudaGetSymbolAddress((void**)&xf2, g_xf2);

    cudaFuncSetAttribute(gemm_k, cudaFuncAttributeMaxDynamicSharedMemorySize, GEMM_SMEM);

    // edge prep
    detect_dtype_k<<<1, 1>>>((const int*)ei);
    zero_deg_k<<<cdiv(N_NODES, TB), TB>>>();
    prep_edges_k<<<cdiv(ET, TB), TB>>>(ei);
    // conv1 GEMM + fused alpha
    gemm_k<<<gemm_grid(256), TB, GEMM_SMEM>>>(x, W1, nullptr, xl, N_NODES, 16, 256, 0, 256, 0, 0,
                                              as1, ad1, 8, 32, nullptr, nullptr, nullptr);
    scan1_k<<<SCAN_G, SCAN_B>>>();
    scan2_k<<<1, 32>>>();
    scan3_k<<<SCAN_G, SCAN_B>>>();
    scatter_k<<<cdiv(ET, TB), TB>>>();

    // ---- conv1: softmax stats + aggregate -> x1 ----
    stats_k<8><<<cdiv(N_NODES, 8), TB>>>();
    agg_k<8, 32><<<cdiv(N_NODES * 2 * 32, TB), TB>>>(xl, b1, x1, 256, 0);

    // dense gg path -> xf0[:, 0:32]
    gemm_k<<<gemm_grid(32), TB, GEMM_SMEM>>>(x,   ln1_w, ln1_b, t32, N_NODES, 16, 32, 1, 32, 0, 0, NOFUSE);
    gemm_k<<<gemm_grid(32), TB, GEMM_SMEM>>>(t32, ln2_w, ln2_b, xf0, N_NODES, 32, 32, 1, 1080, 0, 0, NOFUSE);

    // ---- conv2: GEMM (+fused alpha), stats, aggregate -> x2 ----
    gemm_k<<<gemm_grid(256), TB, GEMM_SMEM>>>(x1, W2, nullptr, xl, N_NODES, 256, 256, 0, 256, 0, 0,
                                              as2, ad2, 8, 32, nullptr, nullptr, nullptr);
    stats_k<8><<<cdiv(N_NODES, 8), TB>>>();
    agg_k<8, 32><<<cdiv(N_NODES * 2 * 32, TB), TB>>>(xl, b2, x2, 256, 0);

    // ---- conv3: GEMM fp16-out (+fused alpha from fp32), stats, agg -> xf0 ----
    gemm_k<<<gemm_grid(768), TB, GEMM_SMEM>>>(x2, W3, nullptr, (float*)xlh, N_NODES, 256, 768, 0, 768, 0, 1,
                                              as3, ad3, 12, 64, nullptr, nullptr, nullptr);
    stats_k<12><<<cdiv(N_NODES, 8), TB>>>();
    agg_h_k<12, 64><<<cdiv(N_NODES * 6 * 32, TB), TB>>>(xlh, b3, xf0, 1080, 32);

    // side dense paths -> xf0[:, 800:880], xf0[:, 880:1080]
    gemm_k<<<gemm_grid(80),  TB, GEMM_SMEM>>>(x1, la1_w, la1_b, xf0, N_NODES, 256, 80, 1, 1080, 800, 0, NOFUSE);
    gemm_k<<<gemm_grid(200), TB, GEMM_SMEM>>>(x2, la3_w, la3_b, xf0, N_NODES, 256, 200, 1, 1080, 880, 0, NOFUSE);

    // MLP head (final sigmoid fused into lf2's epilogue; K=64 -> 1 col tile)
    gemm_k<<<gemm_grid(200), TB, GEMM_SMEM>>>(xf0, lf1_w, lf1_b, xf1, N_NODES, 1080, 200, 1, 200, 0, 0, NOFUSE);
    gemm_k<<<gemm_grid(64),  TB, GEMM_SMEM>>>(xf1, lf2_w, lf2_b, xf2, N_NODES, 200, 64, 1, 64, 0, 0,
                                              nullptr, nullptr, 0, 0, lf3_w, lf3_b, out);
}

// round 15
// speedup vs baseline: 1.8184x; 1.6294x over previous
#include <cuda_runtime.h>
#include <cuda_bf16.h>
#include <mma.h>
#include <math.h>

using namespace nvcuda;
typedef __nv_bfloat16  bf16;
typedef __nv_bfloat162 bf162;

#define N_NODES 50000
#define N_EDGES 400000
#define ET (N_EDGES + N_NODES)   // 450000 edges incl. self-loops
#define TB 256
#define SCAN_B 1024
#define SCAN_G ((N_NODES + SCAN_B - 1) / SCAN_B)   // 49

// ---------------- scratch (device globals; no allocs allowed) ----------------
__device__ bf16  g_xb  [(size_t)N_NODES * 16];    // input x, bf16
__device__ bf16  g_xl  [(size_t)N_NODES * 256];   // conv1/2 transformed
__device__ bf16  g_xl3 [(size_t)N_NODES * 768];   // conv3 transformed
__device__ bf16  g_x1  [(size_t)N_NODES * 256];
__device__ bf16  g_x2  [(size_t)N_NODES * 256];
__device__ bf16  g_t32 [(size_t)N_NODES * 32];
__device__ bf16  g_xf0 [(size_t)N_NODES * 1080];  // [gg | conv3 | xa1 | xa2]
__device__ bf16  g_xf1 [(size_t)N_NODES * 200];
__device__ bf16  g_xf2 [(size_t)N_NODES * 64];    // lf2 out (unused; final fused)
__device__ float g_als [(size_t)N_NODES * 12];
__device__ float g_ald [(size_t)N_NODES * 12];
__device__ float g_m   [(size_t)N_NODES * 12];
__device__ float g_den [(size_t)N_NODES * 12];
__device__ int   g_src[ET];
__device__ int   g_dst[ET];
__device__ int   g_deg[N_NODES];
__device__ int   g_rs [N_NODES + 1];
__device__ int   g_cur[N_NODES];
__device__ int   g_csr[ET];
__device__ int   g_bsum[SCAN_G];
__device__ int   g_boff[SCAN_G];
__device__ int   g_is64;
// bf16 weight copies
__device__ bf16 g_W1h [16 * 256];
__device__ bf16 g_W2h [256 * 256];
__device__ bf16 g_W3h [256 * 768];
__device__ bf16 g_ln1h[16 * 32];
__device__ bf16 g_ln2h[32 * 32];
__device__ bf16 g_la1h[256 * 80];
__device__ bf16 g_la3h[256 * 200];
__device__ bf16 g_lf1h[1080 * 200];
__device__ bf16 g_lf2h[200 * 64];

// ---------------- fp32 -> bf16 conversion -------------------------------------
__global__ void convw_k(const float* __restrict__ s, bf16* __restrict__ d, int n) {
    int i = blockIdx.x * blockDim.x + threadIdx.x;
    if (i < n) d[i] = __float2bfloat16(s[i]);
}

// ---------------- dtype probe ------------------------------------------------
__global__ void detect_dtype_k(const int* __restrict__ ei32) {
    int all_zero = 1;
#pragma unroll
    for (int i = 0; i < 16; i++)
        if (ei32[2 * i + 1] != 0) all_zero = 0;
    g_is64 = all_zero;
}

__global__ void zero_deg_k() {
    int i = blockIdx.x * blockDim.x + threadIdx.x;
    if (i < N_NODES) g_deg[i] = 0;
}

__global__ void prep_edges_k(const void* __restrict__ ei) {
    int i = blockIdx.x * blockDim.x + threadIdx.x;
    if (i >= ET) return;
    int s, d;
    if (i < N_EDGES) {
        if (g_is64) {
            const long long* p = (const long long*)ei;
            s = (int)p[i]; d = (int)p[N_EDGES + i];
        } else {
            const int* p = (const int*)ei;
            s = p[i]; d = p[N_EDGES + i];
        }
    } else {
        s = d = i - N_EDGES;
    }
    g_src[i] = s;
    g_dst[i] = d;
    atomicAdd(&g_deg[d], 1);
}

// ---------------- deterministic 3-phase scan ----------------------------------
__global__ void scan1_k() {
    __shared__ int sh[SCAN_B];
    int b = blockIdx.x, t = threadIdx.x;
    int idx = b * SCAN_B + t;
    int v = (idx < N_NODES) ? g_deg[idx] : 0;
    sh[t] = v;
    __syncthreads();
    for (int o = 1; o < SCAN_B; o <<= 1) {
        int u = (t >= o) ? sh[t - o] : 0;
        __syncthreads();
        sh[t] += u;
        __syncthreads();
    }
    if (idx < N_NODES) g_rs[idx] = sh[t] - v;
    if (t == SCAN_B - 1) g_bsum[b] = sh[t];
}

__global__ void scan2_k() {
    if (threadIdx.x == 0) {
        int run = 0;
        for (int b = 0; b < SCAN_G; b++) { g_boff[b] = run; run += g_bsum[b]; }
    }
}

__global__ void scan3_k() {
    int idx = blockIdx.x * SCAN_B + threadIdx.x;
    if (idx < N_NODES) {
        int v = g_rs[idx] + g_boff[blockIdx.x];
        g_rs[idx] = v;
        g_cur[idx] = v;
    }
    if (idx == 0) g_rs[N_NODES] = ET;
}

__global__ void scatter_k() {
    int e = blockIdx.x * blockDim.x + threadIdx.x;
    if (e >= ET) return;
    int pos = atomicAdd(&g_cur[g_dst[e]], 1);
    g_csr[pos] = g_src[e];
}

// ---------------- bf16 tensor-core GEMM (m16n16k16), cp.async 2-stage ---------
#define BM 128
#define BN 64
#define BK 32
#define A_LD 40            // bf16 elems per A row (80B, pad)
#define B_LD 72            // bf16 elems per B row (144B, pad)
#define A_STG (BM * A_LD)  // 5120 elems
#define B_STG (BK * B_LD)  // 2304 elems
// smem union: stages 2*(5120+2304)*2 = 29696B ; Cs 128*68*4 = 34816B -> 34816 static

__device__ __forceinline__ void cpa16(bf16* dst, const bf16* src, bool valid) {
    unsigned d = (unsigned)__cvta_generic_to_shared(dst);
    int sz = valid ? 16 : 0;                 // src-size 0 => zero-fill 16B
    asm volatile("cp.async.ca.shared.global [%0], [%1], 16, %2;\n"
                 :: "r"(d), "l"(src), "r"(sz));
}

// A [Nr,M] bf16, B [M,K] bf16, C bf16 (ldC/colOff in elems), bias fp32.
// aSrc/aDst: fused GAT alpha from fp32 Cs (heads within one 64-col tile).
// finW: fused final sigmoid head (single column tile, K<=64), finOut fp32.
// Guarantees: M%8==0, K%8==0, colOff%4==0, ldC%4==0.
__global__ void gemm_k(const bf16* __restrict__ A, const bf16* __restrict__ B,
                       const float* __restrict__ bias, bf16* __restrict__ C,
                       int Nr, int M, int K, int act, int ldC, int colOff,
                       const float* __restrict__ aSrc, const float* __restrict__ aDst,
                       int Hh, int Cc,
                       const float* __restrict__ finW, const float* __restrict__ finB,
                       float* __restrict__ finOut) {
    __shared__ __align__(16) unsigned char smem_raw[34816];
    bf16*  As = (bf16*)smem_raw;                          // [2][128][40]
    bf16*  Bs = (bf16*)(smem_raw + 2 * A_STG * 2);        // [2][32][72]
    float* Cs = (float*)smem_raw;                         // [128][68] (aliases)
    int tid = threadIdx.x;
    int wid = tid >> 5;
    int wm = wid >> 1;
    int wn = wid & 1;
    int rowBase = blockIdx.y * BM;
    int colBase = blockIdx.x * BN;

    wmma::fragment<wmma::accumulator, 16, 16, 16, float> acc[2][2];
#pragma unroll
    for (int i = 0; i < 2; i++)
#pragma unroll
        for (int j = 0; j < 2; j++) wmma::fill_fragment(acc[i][j], 0.f);

    int nt = (M + BK - 1) / BK;

    auto load_tile = [&](int k0, int buf) {
        // A: 128 rows x 4 chunks of 8 bf16
#pragma unroll
        for (int i = tid; i < 512; i += 256) {
            int r = i >> 2, c8 = i & 3;
            int gr = rowBase + r, gk = k0 + c8 * 8;
            bool v = (gr < Nr) && (gk + 8 <= M);
            const bf16* src = v ? (A + (size_t)gr * M + gk) : A;
            cpa16(As + buf * A_STG + r * A_LD + c8 * 8, src, v);
        }
        // B: 32 rows x 8 chunks of 8 bf16
        {
            int r = tid >> 3, c8 = tid & 7;
            int gk = k0 + r, gc = colBase + c8 * 8;
            bool v = (gk < M) && (gc + 8 <= K);
            const bf16* src = v ? (B + (size_t)gk * K + gc) : B;
            cpa16(Bs + buf * B_STG + r * B_LD + c8 * 8, src, v);
        }
        asm volatile("cp.async.commit_group;\n");
    };

    load_tile(0, 0);
    for (int t = 0; t < nt; t++) {
        if (t + 1 < nt) {
            load_tile((t + 1) * BK, (t + 1) & 1);
            asm volatile("cp.async.wait_group 1;\n");
        } else {
            asm volatile("cp.async.wait_group 0;\n");
        }
        __syncthreads();
        int buf = t & 1;
        bf16* Ab = As + buf * A_STG;
        bf16* Bb = Bs + buf * B_STG;
#pragma unroll
        for (int ks = 0; ks < 2; ks++) {
            wmma::fragment<wmma::matrix_a, 16, 16, 16, bf16, wmma::row_major> af[2];
            wmma::fragment<wmma::matrix_b, 16, 16, 16, bf16, wmma::row_major> bf[2];
#pragma unroll
            for (int i = 0; i < 2; i++)
                wmma::load_matrix_sync(af[i], Ab + (wm * 32 + i * 16) * A_LD + ks * 16, A_LD);
#pragma unroll
            for (int j = 0; j < 2; j++)
                wmma::load_matrix_sync(bf[j], Bb + (ks * 16) * B_LD + wn * 32 + j * 16, B_LD);
#pragma unroll
            for (int i = 0; i < 2; i++)
#pragma unroll
                for (int j = 0; j < 2; j++)
                    wmma::mma_sync(acc[i][j], af[i], bf[j], acc[i][j]);
        }
        __syncthreads();
    }

    // stage accumulators into (aliased) Cs
#pragma unroll
    for (int i = 0; i < 2; i++)
#pragma unroll
        for (int j = 0; j < 2; j++)
            wmma::store_matrix_sync(Cs + (wm * 32 + i * 16) * 68 + wn * 32 + j * 16,
                                    acc[i][j], 68, wmma::mem_row_major);
    __syncthreads();

    // bias + act in-place (fp32) so fused epilogues see final values
    for (int i = tid; i < BM * BN / 4; i += 256) {
        int r = i >> 4;
        int c4 = (i & 15) << 2;
        int gc = colBase + c4;
        if (gc >= K) continue;
        float4 v = *(const float4*)(Cs + r * 68 + c4);
        if (bias) {
            float4 bb = *(const float4*)(bias + gc);
            v.x += bb.x; v.y += bb.y; v.z += bb.z; v.w += bb.w;
        }
        if (act) {
            v.x = fmaxf(v.x, 0.f); v.y = fmaxf(v.y, 0.f);
            v.z = fmaxf(v.z, 0.f); v.w = fmaxf(v.w, 0.f);
        }
        *(float4*)(Cs + r * 68 + c4) = v;
    }
    __syncthreads();

    // main store: bf16
    for (int i = tid; i < BM * BN / 4; i += 256) {
        int r = i >> 4;
        int c4 = (i & 15) << 2;
        int gr = rowBase + r, gc = colBase + c4;
        if (gr >= Nr || gc >= K) continue;
        float4 v = *(const float4*)(Cs + r * 68 + c4);
        bf162* dst = (bf162*)(C + (size_t)gr * ldC + colOff + gc);
        dst[0] = __floats2bfloat162_rn(v.x, v.y);
        dst[1] = __floats2bfloat162_rn(v.z, v.w);
    }

    // fused GAT alpha (fp32 accumulator values)
    if (aSrc) {
        int nh = BN / Cc;
        for (int t2 = tid; t2 < BM * nh; t2 += 256) {
            int r = t2 % BM, hl = t2 / BM;
            int gr = rowBase + r;
            int h0 = colBase / Cc + hl;
            if (gr >= Nr || h0 >= Hh) continue;
            float s1 = 0.f, s2 = 0.f;
            const float* cr = Cs + r * 68 + hl * Cc;
            const float* asr = aSrc + h0 * Cc;
            const float* adr = aDst + h0 * Cc;
            for (int cc = 0; cc < Cc; cc++) {
                float v = cr[cc];
                s1 += v * asr[cc];
                s2 += v * adr[cc];
            }
            g_als[gr * Hh + h0] = s1;
            g_ald[gr * Hh + h0] = s2;
        }
    }

    // fused final head (single column tile; K<=64)
    if (finW) {
        for (int r = tid; r < BM; r += 256) {
            int gr = rowBase + r;
            if (gr >= Nr) continue;
            float s = 0.f;
            const float* cr = Cs + r * 68;
            for (int cc = 0; cc < K; cc++) s += cr[cc] * finW[cc];
            finOut[gr] = 1.f / (1.f + expf(-(s + finB[0])));
        }
    }
}

__device__ __forceinline__ float lrelu(float v) { return v > 0.f ? v : 0.2f * v; }

// ---------------- stats: per-dst online softmax (m, 1/den) --------------------
template <int H>
__global__ void stats_k() {
    int wid = threadIdx.x >> 5, lane = threadIdx.x & 31;
    int d = blockIdx.x * 8 + wid;
    if (d >= N_NODES) return;
    int beg = g_rs[d], end = g_rs[d + 1];
    float aldv[H];
#pragma unroll
    for (int h = 0; h < H; h++) aldv[h] = g_ald[d * H + h];
    float m[H], s[H];
#pragma unroll
    for (int h = 0; h < H; h++) { m[h] = -1e30f; s[h] = 0.f; }
    for (int j = beg + lane; j < end; j += 32) {
        int src = g_csr[j];
#pragma unroll
        for (int h = 0; h < H; h++) {
            float v = lrelu(g_als[src * H + h] + aldv[h]);
            if (v > m[h]) { s[h] = s[h] * __expf(m[h] - v) + 1.f; m[h] = v; }
            else          { s[h] += __expf(v - m[h]); }
        }
    }
#pragma unroll
    for (int h = 0; h < H; h++) {
#pragma unroll
        for (int o = 16; o; o >>= 1) {
            float mo = __shfl_xor_sync(0xffffffffu, m[h], o);
            float so = __shfl_xor_sync(0xffffffffu, s[h], o);
            float M = fmaxf(m[h], mo);
            s[h] = s[h] * __expf(m[h] - M) + so * __expf(mo - M);
            m[h] = M;
        }
    }
    if (lane == 0) {
#pragma unroll
        for (int h = 0; h < H; h++) {
            g_m[d * H + h] = m[h];
            g_den[d * H + h] = 1.f / s[h];
        }
    }
}

// ---------------- agg (bf16 xl): warp per (dst, 128-elem chunk) ---------------
template <int H, int C>
__global__ void agg_k(const bf16* __restrict__ xl, const float* __restrict__ bias,
                      bf16* __restrict__ out, int ldo, int colOff) {
    const int HC = H * C;
    const int CH = HC / 128;
    int w = (blockIdx.x * blockDim.x + threadIdx.x) >> 5;
    int lane = threadIdx.x & 31;
    if (w >= N_NODES * CH) return;
    int d = w / CH, c = w - d * CH;
    int beg = g_rs[d], end = g_rs[d + 1];
    int col = c * 128 + lane * 4;
    int hm = col / C;
    float ald  = g_ald[d * H + hm];
    float mref = g_m  [d * H + hm];
    float rden = g_den[d * H + hm];
    float4 acc = make_float4(0.f, 0.f, 0.f, 0.f);
    for (int j = beg; j < end; j++) {
        int src = g_csr[j];
        float v = lrelu(g_als[src * H + hm] + ald);
        float coef = __expf(v - mref) * rden;
        const bf162* xr = (const bf162*)(xl + (size_t)src * HC + col);
        float2 p0 = __bfloat1622float2(xr[0]);
        float2 p1 = __bfloat1622float2(xr[1]);
        acc.x += coef * p0.x; acc.y += coef * p0.y;
        acc.z += coef * p1.x; acc.w += coef * p1.y;
    }
    float4 bb = *(const float4*)(bias + col);
    bf162* orow = (bf162*)(out + (size_t)d * ldo + colOff + col);
    orow[0] = __floats2bfloat162_rn(fmaxf(acc.x + bb.x, 0.f), fmaxf(acc.y + bb.y, 0.f));
    orow[1] = __floats2bfloat162_rn(fmaxf(acc.z + bb.z, 0.f), fmaxf(acc.w + bb.w, 0.f));
}

// =============================================================================
static inline dim3 gemm_grid(int K) { return dim3((K + BN - 1) / BN, (N_NODES + BM - 1) / BM); }
static inline int cdiv(int a, int b) { return (a + b - 1) / b; }
#define NOFUSE nullptr, nullptr, 0, 0, nullptr, nullptr, nullptr

extern "C" void kernel_launch(void* const* d_in, const int* in_sizes, int n_in,
                              void* d_out, int out_size) {
    const float* x  = (const float*)d_in[0];
    const void*  ei = d_in[1];
    const float *W1 = (const float*)d_in[2],  *as1 = (const float*)d_in[3],
                *ad1 = (const float*)d_in[4], *b1  = (const float*)d_in[5];
    const float *W2 = (const float*)d_in[6],  *as2 = (const float*)d_in[7],
                *ad2 = (const float*)d_in[8], *b2  = (const float*)d_in[9];
    const float *W3 = (const float*)d_in[10], *as3 = (const float*)d_in[11],
                *ad3 = (const float*)d_in[12], *b3 = (const float*)d_in[13];
    const float *ln1_w = (const float*)d_in[14], *ln1_b = (const float*)d_in[15];
    const float *ln2_w = (const float*)d_in[16], *ln2_b = (const float*)d_in[17];
    const float *la1_w = (const float*)d_in[18], *la1_b = (const float*)d_in[19];
    const float *la3_w = (const float*)d_in[20], *la3_b = (const float*)d_in[21];
    const float *lf1_w = (const float*)d_in[22], *lf1_b = (const float*)d_in[23];
    const float *lf2_w = (const float*)d_in[24], *lf2_b = (const float*)d_in[25];
    const float *lf3_w = (const float*)d_in[26], *lf3_b = (const float*)d_in[27];
    float* out = (float*)d_out;

    bf16 *xb, *xl, *xl3, *x1, *x2, *t32, *xf0, *xf1, *xf2;
    bf16 *W1h, *W2h, *W3h, *ln1h, *ln2h, *la1h, *la3h, *lf1h, *lf2h;
    cudaGetSymbolAddress((void**)&xb,  g_xb);
    cudaGetSymbolAddress((void**)&xl,  g_xl);
    cudaGetSymbolAddress((void**)&xl3, g_xl3);
    cudaGetSymbolAddress((void**)&x1,  g_x1);
    cudaGetSymbolAddress((void**)&x2,  g_x2);
    cudaGetSymbolAddress((void**)&t32, g_t32);
    cudaGetSymbolAddress((void**)&xf0, g_xf0);
    cudaGetSymbolAddress((void**)&xf1, g_xf1);
    cudaGetSymbolAddress((void**)&xf2, g_xf2);
    cudaGetSymbolAddress((void**)&W1h,  g_W1h);
    cudaGetSymbolAddress((void**)&W2h,  g_W2h);
    cudaGetSymbolAddress((void**)&W3h,  g_W3h);
    cudaGetSymbolAddress((void**)&ln1h, g_ln1h);
    cudaGetSymbolAddress((void**)&ln2h, g_ln2h);
    cudaGetSymbolAddress((void**)&la1h, g_la1h);
    cudaGetSymbolAddress((void**)&la3h, g_la3h);
    cudaGetSymbolAddress((void**)&lf1h, g_lf1h);
    cudaGetSymbolAddress((void**)&lf2h, g_lf2h);

    // weight + input conversions
    convw_k<<<cdiv(16 * 256, TB), TB>>>(W1, W1h, 16 * 256);
    convw_k<<<cdiv(256 * 256, TB), TB>>>(W2, W2h, 256 * 256);
    convw_k<<<cdiv(256 * 768, TB), TB>>>(W3, W3h, 256 * 768);
    convw_k<<<cdiv(16 * 32, TB), TB>>>(ln1_w, ln1h, 16 * 32);
    convw_k<<<cdiv(32 * 32, TB), TB>>>(ln2_w, ln2h, 32 * 32);
    convw_k<<<cdiv(256 * 80, TB), TB>>>(la1_w, la1h, 256 * 80);
    convw_k<<<cdiv(256 * 200, TB), TB>>>(la3_w, la3h, 256 * 200);
    convw_k<<<cdiv(1080 * 200, TB), TB>>>(lf1_w, lf1h, 1080 * 200);
    convw_k<<<cdiv(200 * 64, TB), TB>>>(lf2_w, lf2h, 200 * 64);
    convw_k<<<cdiv(N_NODES * 16, TB), TB>>>(x, xb, N_NODES * 16);

    // edge prep
    detect_dtype_k<<<1, 1>>>((const int*)ei);
    zero_deg_k<<<cdiv(N_NODES, TB), TB>>>();
    prep_edges_k<<<cdiv(ET, TB), TB>>>(ei);
    // conv1 GEMM + fused alpha
    gemm_k<<<gemm_grid(256), TB>>>(xb, W1h, nullptr, xl, N_NODES, 16, 256, 0, 256, 0,
                                   as1, ad1, 8, 32, nullptr, nullptr, nullptr);
    scan1_k<<<SCAN_G, SCAN_B>>>();
    scan2_k<<<1, 32>>>();
    scan3_k<<<SCAN_G, SCAN_B>>>();
    scatter_k<<<cdiv(ET, TB), TB>>>();

    // ---- conv1: stats + aggregate -> x1 ----
    stats_k<8><<<cdiv(N_NODES, 8), TB>>>();
    agg_k<8, 32><<<cdiv(N_NODES * 2 * 32, TB), TB>>>(xl, b1, x1, 256, 0);

    // dense gg path -> xf0[:, 0:32]
    gemm_k<<<gemm_grid(32), TB>>>(xb,  ln1h, ln1_b, t32, N_NODES, 16, 32, 1, 32, 0, NOFUSE);
    gemm_k<<<gemm_grid(32), TB>>>(t32, ln2h, ln2_b, xf0, N_NODES, 32, 32, 1, 1080, 0, NOFUSE);

    // ---- conv2: GEMM (+fused alpha), stats, aggregate -> x2 ----
    gemm_k<<<gemm_grid(256), TB>>>(x1, W2h, nullptr, xl, N_NODES, 256, 256, 0, 256, 0,
                                   as2, ad2, 8, 32, nullptr, nullptr, nullptr);
    stats_k<8><<<cdiv(N_NODES, 8), TB>>>();
    agg_k<8, 32><<<cdiv(N_NODES * 2 * 32, TB), TB>>>(xl, b2, x2, 256, 0);

    // ---- conv3: GEMM (+fused alpha), stats, aggregate -> xf0[:, 32:800] ----
    gemm_k<<<gemm_grid(768), TB>>>(x2, W3h, nullptr, xl3, N_NODES, 256, 768, 0, 768, 0,
                                   as3, ad3, 12, 64, nullptr, nullptr, nullptr);
    stats_k<12><<<cdiv(N_NODES, 8), TB>>>();
    agg_k<12, 64><<<cdiv(N_NODES * 6 * 32, TB), TB>>>(xl3, b3, xf0, 1080, 32);

    // side dense paths -> xf0[:, 800:880], xf0[:, 880:1080]
    gemm_k<<<gemm_grid(80),  TB>>>(x1, la1h, la1_b, xf0, N_NODES, 256, 80, 1, 1080, 800, NOFUSE);
    gemm_k<<<gemm_grid(200), TB>>>(x2, la3h, la3_b, xf0, N_NODES, 256, 200, 1, 1080, 880, NOFUSE);

    // MLP head (final sigmoid fused into lf2's epilogue; K=64 -> 1 col tile)
    gemm_k<<<gemm_grid(200), TB>>>(xf0, lf1h, lf1_b, xf1, N_NODES, 1080, 200, 1, 200, 0, NOFUSE);
    gemm_k<<<gemm_grid(64),  TB>>>(xf1, lf2h, lf2_b, xf2, N_NODES, 200, 64, 1, 64, 0,
                                   nullptr, nullptr, 0, 0, lf3_w, lf3_b, out);
}